// round 2
// baseline (speedup 1.0000x reference)
#include <cuda_runtime.h>
#include <cstdint>

// Problem constants (shapes fixed by the dataset; N/E read at runtime).
#define MAXN 100000
#define FIN  128
#define HDIM 64

// Scratch (device globals — no cudaMalloc allowed). float4-typed for 16B align.
__device__ float  g_deg [MAXN];
__device__ float  g_dinv[MAXN];
__device__ float4 g_hs4 [(size_t)MAXN * (HDIM / 4)];  // row-scaled features
__device__ float4 g_agg4[(size_t)MAXN * (HDIM / 4)];  // aggregation accumulator
__device__ int    g_is64;                             // edge-index dtype flag

// ---------------------------------------------------------------------------
// 0) dtype probe: int64 data => first 64 words all in [0, MAXN)
// ---------------------------------------------------------------------------
__global__ void detect_kernel(const void* __restrict__ ei) {
    const long long* p = (const long long*)ei;
    int is64 = 1;
    #pragma unroll 1
    for (int i = 0; i < 64; i++) {
        long long v = p[i];
        if (v < 0 || v >= MAXN) { is64 = 0; break; }
    }
    g_is64 = is64;
}

__device__ __forceinline__ int load_idx(const void* __restrict__ ei, size_t i) {
    if (g_is64) return (int)((const long long*)ei)[i];
    return ((const int*)ei)[i];
}

// ---------------------------------------------------------------------------
// 1) degree: init to 1.0 (self loop), then += 1 per incoming edge (on dst)
// ---------------------------------------------------------------------------
__global__ void init_deg_kernel(int N) {
    int i = blockIdx.x * blockDim.x + threadIdx.x;
    if (i < N) g_deg[i] = 1.0f;
}

__global__ void deg_scatter_kernel(const void* __restrict__ ei, int E) {
    int e = blockIdx.x * blockDim.x + threadIdx.x;
    if (e < E) {
        int dst = load_idx(ei, (size_t)E + e);
        atomicAdd(&g_deg[dst], 1.0f);
    }
}

__global__ void dinv_kernel(int N) {
    int i = blockIdx.x * blockDim.x + threadIdx.x;
    if (i < N) g_dinv[i] = rsqrtf(g_deg[i]);   // deg >= 1 always
}

// ---------------------------------------------------------------------------
// 2) transform1: hs = (x @ W1) * dinv[row];  agg = hs  (self-loop init)
//    block = 256 thr = 8 warps; warp handles 4 rows x (2 cols/lane) = 4x64
// ---------------------------------------------------------------------------
__global__ void transform1_kernel(const float* __restrict__ x,
                                  const float* __restrict__ W1,
                                  int N) {
    __shared__ float Ws[FIN * HDIM];          // 32 KB
    __shared__ float xs[8][4][FIN];           // 16 KB
    const int tid = threadIdx.x;

    for (int i = tid; i < FIN * HDIM / 4; i += 256)
        ((float4*)Ws)[i] = ((const float4*)W1)[i];
    __syncthreads();

    const int w = tid >> 5, l = tid & 31;
    const int rowBase = blockIdx.x * 32 + w * 4;

    #pragma unroll
    for (int r = 0; r < 4; r++) {
        int row = rowBase + r;
        if (row < N)
            ((float4*)xs[w][r])[l] = ((const float4*)(x + (size_t)row * FIN))[l];
    }
    __syncwarp();

    float2 acc[4] = {{0.f,0.f},{0.f,0.f},{0.f,0.f},{0.f,0.f}};
    const float2* Ws2 = (const float2*)Ws;
    #pragma unroll 8
    for (int k = 0; k < FIN; k++) {
        float2 wv = Ws2[k * 32 + l];          // cols (2l, 2l+1)
        #pragma unroll
        for (int r = 0; r < 4; r++) {
            float xv = xs[w][r][k];           // smem broadcast
            acc[r].x = fmaf(xv, wv.x, acc[r].x);
            acc[r].y = fmaf(xv, wv.y, acc[r].y);
        }
    }

    float* g_hs  = (float*)g_hs4;
    float* g_agg = (float*)g_agg4;
    #pragma unroll
    for (int r = 0; r < 4; r++) {
        int row = rowBase + r;
        if (row < N) {
            float d = g_dinv[row];
            float2 h = {acc[r].x * d, acc[r].y * d};
            ((float2*)(g_hs  + (size_t)row * HDIM))[l] = h;
            ((float2*)(g_agg + (size_t)row * HDIM))[l] = h;   // self-loop term
        }
    }
}

// ---------------------------------------------------------------------------
// 3) edge scatter: agg[dst] += hs[src]   (64 floats, 16 threads/edge, red.v4)
// ---------------------------------------------------------------------------
__global__ void scatter_kernel(const void* __restrict__ ei, int E) {
    int t = blockIdx.x * blockDim.x + threadIdx.x;
    int e = t >> 4;
    if (e >= E) return;
    int q = t & 15;
    int src = load_idx(ei, e);
    int dst = load_idx(ei, (size_t)E + e);
    const float4 v = g_hs4[(size_t)src * 16 + q];
    float4* p = &g_agg4[(size_t)dst * 16 + q];
    asm volatile("red.global.add.v4.f32 [%0], {%1,%2,%3,%4};"
                 :: "l"(p), "f"(v.x), "f"(v.y), "f"(v.z), "f"(v.w)
                 : "memory");
}

// ---------------------------------------------------------------------------
// 4) transform2: t = relu(dinv*agg1 + b1); h2 = t @ W2;
//    hs = h2 * dinv; agg = hs (in-place over agg — own-row read-then-write)
// ---------------------------------------------------------------------------
__global__ void transform2_kernel(const float* __restrict__ W2,
                                  const float* __restrict__ b1,
                                  int N) {
    __shared__ float Ws[HDIM * HDIM];         // 16 KB
    __shared__ float ts[8][4][HDIM];          // 8 KB
    const int tid = threadIdx.x;

    for (int i = tid; i < HDIM * HDIM / 4; i += 256)
        ((float4*)Ws)[i] = ((const float4*)W2)[i];
    __syncthreads();

    const int w = tid >> 5, l = tid & 31;
    const int rowBase = blockIdx.x * 32 + w * 4;
    const float2 bv = ((const float2*)b1)[l];

    float* g_hs  = (float*)g_hs4;
    float* g_agg = (float*)g_agg4;

    #pragma unroll
    for (int r = 0; r < 4; r++) {
        int row = rowBase + r;
        if (row < N) {
            float d = g_dinv[row];
            float2 av = ((const float2*)(g_agg + (size_t)row * HDIM))[l];
            float2 tv;
            tv.x = fmaxf(fmaf(d, av.x, bv.x), 0.f);
            tv.y = fmaxf(fmaf(d, av.y, bv.y), 0.f);
            ((float2*)ts[w][r])[l] = tv;
        }
    }
    __syncwarp();

    float2 acc[4] = {{0.f,0.f},{0.f,0.f},{0.f,0.f},{0.f,0.f}};
    const float2* Ws2 = (const float2*)Ws;
    #pragma unroll 8
    for (int k = 0; k < HDIM; k++) {
        float2 wv = Ws2[k * 32 + l];
        #pragma unroll
        for (int r = 0; r < 4; r++) {
            float tv = ts[w][r][k];
            acc[r].x = fmaf(tv, wv.x, acc[r].x);
            acc[r].y = fmaf(tv, wv.y, acc[r].y);
        }
    }

    #pragma unroll
    for (int r = 0; r < 4; r++) {
        int row = rowBase + r;
        if (row < N) {
            float d = g_dinv[row];
            float2 h = {acc[r].x * d, acc[r].y * d};
            ((float2*)(g_hs  + (size_t)row * HDIM))[l] = h;
            ((float2*)(g_agg + (size_t)row * HDIM))[l] = h;
        }
    }
}

// ---------------------------------------------------------------------------
// 5) final: out[i] = relu(dinv*agg2 + b2) @ Wlin + blin   (warp per row)
// ---------------------------------------------------------------------------
__global__ void final_kernel(const float* __restrict__ b2,
                             const float* __restrict__ Wlin,
                             const float* __restrict__ blin,
                             float* __restrict__ out, int N) {
    int warpG = (blockIdx.x * blockDim.x + threadIdx.x) >> 5;
    int l = threadIdx.x & 31;
    if (warpG >= N) return;
    int row = warpG;
    const float* g_agg = (const float*)g_agg4;
    float d = g_dinv[row];
    float2 av = ((const float2*)(g_agg + (size_t)row * HDIM))[l];
    float2 bv = ((const float2*)b2)[l];
    float2 wv = ((const float2*)Wlin)[l];
    float h0 = fmaxf(fmaf(d, av.x, bv.x), 0.f);
    float h1 = fmaxf(fmaf(d, av.y, bv.y), 0.f);
    float s = h0 * wv.x + h1 * wv.y;
    #pragma unroll
    for (int off = 16; off > 0; off >>= 1)
        s += __shfl_xor_sync(0xFFFFFFFFu, s, off);
    if (l == 0) out[row] = s + blin[0];
}

// ---------------------------------------------------------------------------
extern "C" void kernel_launch(void* const* d_in, const int* in_sizes, int n_in,
                              void* d_out, int out_size) {
    const float* x    = (const float*)d_in[0];
    const void*  ei   = d_in[1];
    const float* W1   = (const float*)d_in[2];
    const float* b1   = (const float*)d_in[3];
    const float* W2   = (const float*)d_in[4];
    const float* b2   = (const float*)d_in[5];
    const float* Wlin = (const float*)d_in[6];
    const float* blin = (const float*)d_in[7];
    float*       out  = (float*)d_out;

    const int N = in_sizes[0] / FIN;
    const int E = in_sizes[1] / 2;

    const int nb  = (N + 255) / 256;
    const int eb  = (E + 255) / 256;
    const int sb  = (E * 16 + 255) / 256;
    const int tb  = (N + 31) / 32;          // 32 rows per block
    const int fb  = (N + 7) / 8;            // 8 rows per block (warp/row)

    detect_kernel     <<<1, 1>>>(ei);
    init_deg_kernel   <<<nb, 256>>>(N);
    deg_scatter_kernel<<<eb, 256>>>(ei, E);
    dinv_kernel       <<<nb, 256>>>(N);

    transform1_kernel <<<tb, 256>>>(x, W1, N);
    scatter_kernel    <<<sb, 256>>>(ei, E);

    transform2_kernel <<<tb, 256>>>(W2, b1, N);
    scatter_kernel    <<<sb, 256>>>(ei, E);

    final_kernel      <<<fb, 256>>>(b2, Wlin, blin, out, N);
}

// round 3
// speedup vs baseline: 1.6510x; 1.6510x over previous
#include <cuda_runtime.h>
#include <cstdint>

#define MAXN 100000
#define MAXE 3200000
#define FIN  128
#define HDIM 64
#define SCAN_B 256

// Scratch (device globals — no cudaMalloc allowed).
__device__ float  g_deg  [MAXN];
__device__ float  g_dinv [MAXN];
__device__ int    g_fillc[MAXN];
__device__ int    g_rowptr[MAXN + 1];
__device__ int    g_bsum [(MAXN + SCAN_B - 1) / SCAN_B + 1];
__device__ int    g_adj  [MAXE];
__device__ float4 g_hs4 [(size_t)MAXN * (HDIM / 4)];  // row-scaled features
__device__ float4 g_agg4[(size_t)MAXN * (HDIM / 4)];  // aggregation result
__device__ int    g_is64;                             // edge-index dtype flag

// ---------------------------------------------------------------------------
// 0) dtype probe: int64 data => first 64 words all in [0, MAXN)
// ---------------------------------------------------------------------------
__global__ void detect_kernel(const void* __restrict__ ei) {
    const long long* p = (const long long*)ei;
    int is64 = 1;
    #pragma unroll 1
    for (int i = 0; i < 64; i++) {
        long long v = p[i];
        if (v < 0 || v >= MAXN) { is64 = 0; break; }
    }
    g_is64 = is64;
}

__device__ __forceinline__ int load_idx(const void* __restrict__ ei, size_t i) {
    if (g_is64) return (int)((const long long*)ei)[i];
    return ((const int*)ei)[i];
}

// ---------------------------------------------------------------------------
// 1) degree histogram (self loop baked in as +1) and fill-counter init
// ---------------------------------------------------------------------------
__global__ void init_deg_kernel(int N) {
    int i = blockIdx.x * blockDim.x + threadIdx.x;
    if (i < N) { g_deg[i] = 1.0f; g_fillc[i] = 0; }
}

__global__ void deg_scatter_kernel(const void* __restrict__ ei, int E) {
    int e = blockIdx.x * blockDim.x + threadIdx.x;
    if (e < E) {
        int dst = load_idx(ei, (size_t)E + e);
        atomicAdd(&g_deg[dst], 1.0f);
    }
}

__global__ void dinv_kernel(int N) {
    int i = blockIdx.x * blockDim.x + threadIdx.x;
    if (i < N) g_dinv[i] = rsqrtf(g_deg[i]);   // deg >= 1 always
}

// ---------------------------------------------------------------------------
// 2) CSR build: exclusive scan of edge counts (deg-1), then fill adj with src
// ---------------------------------------------------------------------------
__global__ void scan1_kernel(int N) {
    __shared__ int s[SCAN_B];
    int i = blockIdx.x * SCAN_B + threadIdx.x;
    int v = (i < N) ? (int)(g_deg[i]) - 1 : 0;   // edge count into node i
    s[threadIdx.x] = v;
    __syncthreads();
    // Hillis-Steele inclusive scan
    #pragma unroll
    for (int off = 1; off < SCAN_B; off <<= 1) {
        int t = (threadIdx.x >= off) ? s[threadIdx.x - off] : 0;
        __syncthreads();
        s[threadIdx.x] += t;
        __syncthreads();
    }
    if (i < N) g_rowptr[i] = s[threadIdx.x] - v;            // exclusive
    if (threadIdx.x == SCAN_B - 1) g_bsum[blockIdx.x] = s[SCAN_B - 1];
}

__global__ void scan2_kernel(int nblocks) {
    __shared__ int s[512];
    int v = (threadIdx.x < nblocks) ? g_bsum[threadIdx.x] : 0;
    s[threadIdx.x] = v;
    __syncthreads();
    #pragma unroll
    for (int off = 1; off < 512; off <<= 1) {
        int t = (threadIdx.x >= off) ? s[threadIdx.x - off] : 0;
        __syncthreads();
        s[threadIdx.x] += t;
        __syncthreads();
    }
    if (threadIdx.x < nblocks) g_bsum[threadIdx.x] = s[threadIdx.x] - v;  // exclusive
}

__global__ void scan3_kernel(int N, int E) {
    int i = blockIdx.x * SCAN_B + threadIdx.x;
    if (i < N) g_rowptr[i] += g_bsum[blockIdx.x];
    if (i == 0) g_rowptr[N] = E;
}

__global__ void fill_kernel(const void* __restrict__ ei, int E) {
    int e = blockIdx.x * blockDim.x + threadIdx.x;
    if (e < E) {
        int src = load_idx(ei, e);
        int dst = load_idx(ei, (size_t)E + e);
        int pos = atomicAdd(&g_fillc[dst], 1);
        g_adj[g_rowptr[dst] + pos] = src;
    }
}

// ---------------------------------------------------------------------------
// 3) transform1: hs = (x @ W1) * dinv[row]
// ---------------------------------------------------------------------------
__global__ void transform1_kernel(const float* __restrict__ x,
                                  const float* __restrict__ W1,
                                  int N) {
    __shared__ float Ws[FIN * HDIM];          // 32 KB
    __shared__ float xs[8][4][FIN];           // 16 KB
    const int tid = threadIdx.x;

    for (int i = tid; i < FIN * HDIM / 4; i += 256)
        ((float4*)Ws)[i] = ((const float4*)W1)[i];
    __syncthreads();

    const int w = tid >> 5, l = tid & 31;
    const int rowBase = blockIdx.x * 32 + w * 4;

    #pragma unroll
    for (int r = 0; r < 4; r++) {
        int row = rowBase + r;
        if (row < N)
            ((float4*)xs[w][r])[l] = ((const float4*)(x + (size_t)row * FIN))[l];
    }
    __syncwarp();

    float2 acc[4] = {{0.f,0.f},{0.f,0.f},{0.f,0.f},{0.f,0.f}};
    const float2* Ws2 = (const float2*)Ws;
    #pragma unroll 8
    for (int k = 0; k < FIN; k++) {
        float2 wv = Ws2[k * 32 + l];
        #pragma unroll
        for (int r = 0; r < 4; r++) {
            float xv = xs[w][r][k];
            acc[r].x = fmaf(xv, wv.x, acc[r].x);
            acc[r].y = fmaf(xv, wv.y, acc[r].y);
        }
    }

    float* g_hs = (float*)g_hs4;
    #pragma unroll
    for (int r = 0; r < 4; r++) {
        int row = rowBase + r;
        if (row < N) {
            float d = g_dinv[row];
            float2 h = {acc[r].x * d, acc[r].y * d};
            ((float2*)(g_hs + (size_t)row * HDIM))[l] = h;
        }
    }
}

// ---------------------------------------------------------------------------
// 4) aggregation (gather): agg[i] = hs[i] + sum_{src in adj(i)} hs[src]
//    warp per node; 32 coalesced index loads, shfl broadcast, float2/lane
// ---------------------------------------------------------------------------
__global__ void agg_kernel(int N) {
    int warp = (blockIdx.x * blockDim.x + threadIdx.x) >> 5;
    if (warp >= N) return;
    const int node = warp;
    const int l = threadIdx.x & 31;
    const float2* hs2 = (const float2*)g_hs4;

    float2 acc = hs2[(size_t)node * 32 + l];       // self loop
    int beg = g_rowptr[node], end = g_rowptr[node + 1];

    int j = beg;
    for (; j + 32 <= end; j += 32) {
        int idx = g_adj[j + l];
        #pragma unroll
        for (int k = 0; k < 32; k++) {
            int s = __shfl_sync(0xFFFFFFFFu, idx, k);
            float2 v = hs2[(size_t)s * 32 + l];
            acc.x += v.x; acc.y += v.y;
        }
    }
    if (j < end) {
        int idx = (j + l < end) ? g_adj[j + l] : 0;
        int n = end - j;
        #pragma unroll 4
        for (int k = 0; k < n; k++) {
            int s = __shfl_sync(0xFFFFFFFFu, idx, k);
            float2 v = hs2[(size_t)s * 32 + l];
            acc.x += v.x; acc.y += v.y;
        }
    }
    ((float2*)g_agg4)[(size_t)node * 32 + l] = acc;
}

// ---------------------------------------------------------------------------
// 5) transform2: t = relu(dinv*agg1 + b1); hs = (t @ W2) * dinv
// ---------------------------------------------------------------------------
__global__ void transform2_kernel(const float* __restrict__ W2,
                                  const float* __restrict__ b1,
                                  int N) {
    __shared__ float Ws[HDIM * HDIM];         // 16 KB
    __shared__ float ts[8][4][HDIM];          // 8 KB
    const int tid = threadIdx.x;

    for (int i = tid; i < HDIM * HDIM / 4; i += 256)
        ((float4*)Ws)[i] = ((const float4*)W2)[i];
    __syncthreads();

    const int w = tid >> 5, l = tid & 31;
    const int rowBase = blockIdx.x * 32 + w * 4;
    const float2 bv = ((const float2*)b1)[l];

    float* g_hs  = (float*)g_hs4;
    const float* g_agg = (const float*)g_agg4;

    #pragma unroll
    for (int r = 0; r < 4; r++) {
        int row = rowBase + r;
        if (row < N) {
            float d = g_dinv[row];
            float2 av = ((const float2*)(g_agg + (size_t)row * HDIM))[l];
            float2 tv;
            tv.x = fmaxf(fmaf(d, av.x, bv.x), 0.f);
            tv.y = fmaxf(fmaf(d, av.y, bv.y), 0.f);
            ((float2*)ts[w][r])[l] = tv;
        }
    }
    __syncwarp();

    float2 acc[4] = {{0.f,0.f},{0.f,0.f},{0.f,0.f},{0.f,0.f}};
    const float2* Ws2 = (const float2*)Ws;
    #pragma unroll 8
    for (int k = 0; k < HDIM; k++) {
        float2 wv = Ws2[k * 32 + l];
        #pragma unroll
        for (int r = 0; r < 4; r++) {
            float tv = ts[w][r][k];
            acc[r].x = fmaf(tv, wv.x, acc[r].x);
            acc[r].y = fmaf(tv, wv.y, acc[r].y);
        }
    }

    #pragma unroll
    for (int r = 0; r < 4; r++) {
        int row = rowBase + r;
        if (row < N) {
            float d = g_dinv[row];
            float2 h = {acc[r].x * d, acc[r].y * d};
            ((float2*)(g_hs + (size_t)row * HDIM))[l] = h;
        }
    }
}

// ---------------------------------------------------------------------------
// 6) final: out[i] = relu(dinv*agg2 + b2) @ Wlin + blin   (warp per row)
// ---------------------------------------------------------------------------
__global__ void final_kernel(const float* __restrict__ b2,
                             const float* __restrict__ Wlin,
                             const float* __restrict__ blin,
                             float* __restrict__ out, int N) {
    int warpG = (blockIdx.x * blockDim.x + threadIdx.x) >> 5;
    int l = threadIdx.x & 31;
    if (warpG >= N) return;
    int row = warpG;
    const float* g_agg = (const float*)g_agg4;
    float d = g_dinv[row];
    float2 av = ((const float2*)(g_agg + (size_t)row * HDIM))[l];
    float2 bv = ((const float2*)b2)[l];
    float2 wv = ((const float2*)Wlin)[l];
    float h0 = fmaxf(fmaf(d, av.x, bv.x), 0.f);
    float h1 = fmaxf(fmaf(d, av.y, bv.y), 0.f);
    float s = h0 * wv.x + h1 * wv.y;
    #pragma unroll
    for (int off = 16; off > 0; off >>= 1)
        s += __shfl_xor_sync(0xFFFFFFFFu, s, off);
    if (l == 0) out[row] = s + blin[0];
}

// ---------------------------------------------------------------------------
extern "C" void kernel_launch(void* const* d_in, const int* in_sizes, int n_in,
                              void* d_out, int out_size) {
    const float* x    = (const float*)d_in[0];
    const void*  ei   = d_in[1];
    const float* W1   = (const float*)d_in[2];
    const float* b1   = (const float*)d_in[3];
    const float* W2   = (const float*)d_in[4];
    const float* b2   = (const float*)d_in[5];
    const float* Wlin = (const float*)d_in[6];
    const float* blin = (const float*)d_in[7];
    float*       out  = (float*)d_out;

    const int N = in_sizes[0] / FIN;
    const int E = in_sizes[1] / 2;

    const int nb  = (N + SCAN_B - 1) / SCAN_B;   // scan blocks
    const int eb  = (E + 255) / 256;
    const int tb  = (N + 31) / 32;               // 32 rows per block
    const int ab  = (N * 32 + 255) / 256;        // warp per node
    const int fb  = (N + 7) / 8;

    detect_kernel     <<<1, 1>>>(ei);
    init_deg_kernel   <<<nb, SCAN_B>>>(N);
    deg_scatter_kernel<<<eb, 256>>>(ei, E);
    dinv_kernel       <<<nb, SCAN_B>>>(N);

    scan1_kernel      <<<nb, SCAN_B>>>(N);
    scan2_kernel      <<<1, 512>>>(nb);
    scan3_kernel      <<<nb, SCAN_B>>>(N, E);
    fill_kernel       <<<eb, 256>>>(ei, E);

    transform1_kernel <<<tb, 256>>>(x, W1, N);
    agg_kernel        <<<ab, 256>>>(N);

    transform2_kernel <<<tb, 256>>>(W2, b1, N);
    agg_kernel        <<<ab, 256>>>(N);

    final_kernel      <<<fb, 256>>>(b2, Wlin, blin, out, N);
}

// round 4
// speedup vs baseline: 1.6731x; 1.0134x over previous
#include <cuda_runtime.h>
#include <cuda_fp16.h>
#include <cstdint>

#define MAXN 100000
#define MAXE 3200000
#define FIN  128
#define HDIM 64
#define SCAN_B 256

// Scratch (device globals — no cudaMalloc allowed).
__device__ float   g_deg  [MAXN];
__device__ float   g_dinv [MAXN];
__device__ int     g_fillc[MAXN];
__device__ int     g_rowptr[MAXN + 1];
__device__ int     g_bsum [(MAXN + SCAN_B - 1) / SCAN_B + 1];
__device__ int     g_adj  [MAXE];
__device__ __half2 g_hsh [(size_t)MAXN * (HDIM / 2)];  // row-scaled messages (fp16)
__device__ float4  g_agg4[(size_t)MAXN * (HDIM / 4)];  // aggregation result (fp32)
__device__ int     g_is64;                             // edge-index dtype flag

// ---------------------------------------------------------------------------
// 0) dtype probe: int64 data => first 64 words all in [0, MAXN)
// ---------------------------------------------------------------------------
__global__ void detect_kernel(const void* __restrict__ ei) {
    const long long* p = (const long long*)ei;
    int is64 = 1;
    #pragma unroll 1
    for (int i = 0; i < 64; i++) {
        long long v = p[i];
        if (v < 0 || v >= MAXN) { is64 = 0; break; }
    }
    g_is64 = is64;
}

__device__ __forceinline__ int load_idx(const void* __restrict__ ei, size_t i) {
    if (g_is64) return (int)((const long long*)ei)[i];
    return ((const int*)ei)[i];
}

// ---------------------------------------------------------------------------
// 1) degree histogram (self loop baked in as +1) and fill-counter init
// ---------------------------------------------------------------------------
__global__ void init_deg_kernel(int N) {
    int i = blockIdx.x * blockDim.x + threadIdx.x;
    if (i < N) { g_deg[i] = 1.0f; g_fillc[i] = 0; }
}

__global__ void deg_scatter_kernel(const void* __restrict__ ei, int E) {
    int e = blockIdx.x * blockDim.x + threadIdx.x;
    if (e < E) {
        int dst = load_idx(ei, (size_t)E + e);
        atomicAdd(&g_deg[dst], 1.0f);
    }
}

// ---------------------------------------------------------------------------
// 2) CSR build: exclusive scan of edge counts (deg-1), then fill adj with src
//    (dinv computed in scan1 — one less kernel)
// ---------------------------------------------------------------------------
__global__ void scan1_kernel(int N) {
    __shared__ int s[SCAN_B];
    int i = blockIdx.x * SCAN_B + threadIdx.x;
    float degv = (i < N) ? g_deg[i] : 1.0f;
    if (i < N) g_dinv[i] = rsqrtf(degv);
    int v = (i < N) ? (int)degv - 1 : 0;         // edge count into node i
    s[threadIdx.x] = v;
    __syncthreads();
    #pragma unroll
    for (int off = 1; off < SCAN_B; off <<= 1) {
        int t = (threadIdx.x >= off) ? s[threadIdx.x - off] : 0;
        __syncthreads();
        s[threadIdx.x] += t;
        __syncthreads();
    }
    if (i < N) g_rowptr[i] = s[threadIdx.x] - v;            // exclusive
    if (threadIdx.x == SCAN_B - 1) g_bsum[blockIdx.x] = s[SCAN_B - 1];
}

__global__ void scan2_kernel(int nblocks) {
    __shared__ int s[512];
    int v = (threadIdx.x < nblocks) ? g_bsum[threadIdx.x] : 0;
    s[threadIdx.x] = v;
    __syncthreads();
    #pragma unroll
    for (int off = 1; off < 512; off <<= 1) {
        int t = (threadIdx.x >= off) ? s[threadIdx.x - off] : 0;
        __syncthreads();
        s[threadIdx.x] += t;
        __syncthreads();
    }
    if (threadIdx.x < nblocks) g_bsum[threadIdx.x] = s[threadIdx.x] - v;  // exclusive
}

__global__ void scan3_kernel(int N, int E) {
    int i = blockIdx.x * SCAN_B + threadIdx.x;
    if (i < N) g_rowptr[i] += g_bsum[blockIdx.x];
    if (i == 0) g_rowptr[N] = E;
}

__global__ void fill_kernel(const void* __restrict__ ei, int E) {
    int e = blockIdx.x * blockDim.x + threadIdx.x;
    if (e < E) {
        int src = load_idx(ei, e);
        int dst = load_idx(ei, (size_t)E + e);
        int pos = atomicAdd(&g_fillc[dst], 1);
        g_adj[g_rowptr[dst] + pos] = src;
    }
}

// ---------------------------------------------------------------------------
// 3) transform1: hs = half((x @ W1) * dinv[row])
// ---------------------------------------------------------------------------
__global__ void transform1_kernel(const float* __restrict__ x,
                                  const float* __restrict__ W1,
                                  int N) {
    __shared__ float Ws[FIN * HDIM];          // 32 KB
    __shared__ float xs[8][4][FIN];           // 16 KB
    const int tid = threadIdx.x;

    for (int i = tid; i < FIN * HDIM / 4; i += 256)
        ((float4*)Ws)[i] = ((const float4*)W1)[i];
    __syncthreads();

    const int w = tid >> 5, l = tid & 31;
    const int rowBase = blockIdx.x * 32 + w * 4;

    #pragma unroll
    for (int r = 0; r < 4; r++) {
        int row = rowBase + r;
        if (row < N)
            ((float4*)xs[w][r])[l] = ((const float4*)(x + (size_t)row * FIN))[l];
    }
    __syncwarp();

    float2 acc[4] = {{0.f,0.f},{0.f,0.f},{0.f,0.f},{0.f,0.f}};
    const float2* Ws2 = (const float2*)Ws;
    #pragma unroll 8
    for (int k = 0; k < FIN; k++) {
        float2 wv = Ws2[k * 32 + l];
        #pragma unroll
        for (int r = 0; r < 4; r++) {
            float xv = xs[w][r][k];
            acc[r].x = fmaf(xv, wv.x, acc[r].x);
            acc[r].y = fmaf(xv, wv.y, acc[r].y);
        }
    }

    #pragma unroll
    for (int r = 0; r < 4; r++) {
        int row = rowBase + r;
        if (row < N) {
            float d = g_dinv[row];
            g_hsh[(size_t)row * 32 + l] =
                __floats2half2_rn(acc[r].x * d, acc[r].y * d);
        }
    }
}

// ---------------------------------------------------------------------------
// 4) aggregation (gather): agg[i] = hs[i] + sum_{src in adj(i)} hs[src]
//    warp per node; fp16 messages (128 B/row, one L2 line), fp32 accum
// ---------------------------------------------------------------------------
__global__ void agg_kernel(int N) {
    int warp = (blockIdx.x * blockDim.x + threadIdx.x) >> 5;
    if (warp >= N) return;
    const int node = warp;
    const int l = threadIdx.x & 31;

    float2 acc = __half22float2(g_hsh[(size_t)node * 32 + l]);   // self loop
    int beg = g_rowptr[node], end = g_rowptr[node + 1];

    int j = beg;
    for (; j + 32 <= end; j += 32) {
        int idx = g_adj[j + l];
        #pragma unroll
        for (int k = 0; k < 32; k++) {
            int s = __shfl_sync(0xFFFFFFFFu, idx, k);
            float2 v = __half22float2(g_hsh[(size_t)s * 32 + l]);
            acc.x += v.x; acc.y += v.y;
        }
    }
    if (j < end) {
        int idx = (j + l < end) ? g_adj[j + l] : 0;
        int n = end - j;
        #pragma unroll 4
        for (int k = 0; k < n; k++) {
            int s = __shfl_sync(0xFFFFFFFFu, idx, k);
            float2 v = __half22float2(g_hsh[(size_t)s * 32 + l]);
            acc.x += v.x; acc.y += v.y;
        }
    }
    ((float2*)g_agg4)[(size_t)node * 32 + l] = acc;
}

// ---------------------------------------------------------------------------
// 5) transform2: t = relu(dinv*agg1 + b1); hs = half((t @ W2) * dinv)
// ---------------------------------------------------------------------------
__global__ void transform2_kernel(const float* __restrict__ W2,
                                  const float* __restrict__ b1,
                                  int N) {
    __shared__ float Ws[HDIM * HDIM];         // 16 KB
    __shared__ float ts[8][4][HDIM];          // 8 KB
    const int tid = threadIdx.x;

    for (int i = tid; i < HDIM * HDIM / 4; i += 256)
        ((float4*)Ws)[i] = ((const float4*)W2)[i];
    __syncthreads();

    const int w = tid >> 5, l = tid & 31;
    const int rowBase = blockIdx.x * 32 + w * 4;
    const float2 bv = ((const float2*)b1)[l];
    const float* g_agg = (const float*)g_agg4;

    #pragma unroll
    for (int r = 0; r < 4; r++) {
        int row = rowBase + r;
        if (row < N) {
            float d = g_dinv[row];
            float2 av = ((const float2*)(g_agg + (size_t)row * HDIM))[l];
            float2 tv;
            tv.x = fmaxf(fmaf(d, av.x, bv.x), 0.f);
            tv.y = fmaxf(fmaf(d, av.y, bv.y), 0.f);
            ((float2*)ts[w][r])[l] = tv;
        }
    }
    __syncwarp();

    float2 acc[4] = {{0.f,0.f},{0.f,0.f},{0.f,0.f},{0.f,0.f}};
    const float2* Ws2 = (const float2*)Ws;
    #pragma unroll 8
    for (int k = 0; k < HDIM; k++) {
        float2 wv = Ws2[k * 32 + l];
        #pragma unroll
        for (int r = 0; r < 4; r++) {
            float tv = ts[w][r][k];
            acc[r].x = fmaf(tv, wv.x, acc[r].x);
            acc[r].y = fmaf(tv, wv.y, acc[r].y);
        }
    }

    #pragma unroll
    for (int r = 0; r < 4; r++) {
        int row = rowBase + r;
        if (row < N) {
            float d = g_dinv[row];
            g_hsh[(size_t)row * 32 + l] =
                __floats2half2_rn(acc[r].x * d, acc[r].y * d);
        }
    }
}

// ---------------------------------------------------------------------------
// 6) final: out[i] = relu(dinv*agg2 + b2) @ Wlin + blin   (warp per row)
// ---------------------------------------------------------------------------
__global__ void final_kernel(const float* __restrict__ b2,
                             const float* __restrict__ Wlin,
                             const float* __restrict__ blin,
                             float* __restrict__ out, int N) {
    int warpG = (blockIdx.x * blockDim.x + threadIdx.x) >> 5;
    int l = threadIdx.x & 31;
    if (warpG >= N) return;
    int row = warpG;
    const float* g_agg = (const float*)g_agg4;
    float d = g_dinv[row];
    float2 av = ((const float2*)(g_agg + (size_t)row * HDIM))[l];
    float2 bv = ((const float2*)b2)[l];
    float2 wv = ((const float2*)Wlin)[l];
    float h0 = fmaxf(fmaf(d, av.x, bv.x), 0.f);
    float h1 = fmaxf(fmaf(d, av.y, bv.y), 0.f);
    float s = h0 * wv.x + h1 * wv.y;
    #pragma unroll
    for (int off = 16; off > 0; off >>= 1)
        s += __shfl_xor_sync(0xFFFFFFFFu, s, off);
    if (l == 0) out[row] = s + blin[0];
}

// ---------------------------------------------------------------------------
extern "C" void kernel_launch(void* const* d_in, const int* in_sizes, int n_in,
                              void* d_out, int out_size) {
    const float* x    = (const float*)d_in[0];
    const void*  ei   = d_in[1];
    const float* W1   = (const float*)d_in[2];
    const float* b1   = (const float*)d_in[3];
    const float* W2   = (const float*)d_in[4];
    const float* b2   = (const float*)d_in[5];
    const float* Wlin = (const float*)d_in[6];
    const float* blin = (const float*)d_in[7];
    float*       out  = (float*)d_out;

    const int N = in_sizes[0] / FIN;
    const int E = in_sizes[1] / 2;

    const int nb  = (N + SCAN_B - 1) / SCAN_B;   // scan blocks
    const int eb  = (E + 255) / 256;
    const int tb  = (N + 31) / 32;               // 32 rows per block
    const int ab  = (N * 32 + 255) / 256;        // warp per node
    const int fb  = (N + 7) / 8;

    detect_kernel     <<<1, 1>>>(ei);
    init_deg_kernel   <<<nb, SCAN_B>>>(N);
    deg_scatter_kernel<<<eb, 256>>>(ei, E);

    scan1_kernel      <<<nb, SCAN_B>>>(N);
    scan2_kernel      <<<1, 512>>>(nb);
    scan3_kernel      <<<nb, SCAN_B>>>(N, E);
    fill_kernel       <<<eb, 256>>>(ei, E);

    transform1_kernel <<<tb, 256>>>(x, W1, N);
    agg_kernel        <<<ab, 256>>>(N);

    transform2_kernel <<<tb, 256>>>(W2, b1, N);
    agg_kernel        <<<ab, 256>>>(N);

    final_kernel      <<<fb, 256>>>(b2, Wlin, blin, out, N);
}

// round 5
// speedup vs baseline: 1.7324x; 1.0354x over previous
#include <cuda_runtime.h>
#include <cuda_fp16.h>
#include <cstdint>

#define MAXN 100000
#define MAXE 3200000
#define FIN  128
#define HDIM 64
#define SCAN_B 256

// Scratch (device globals — no cudaMalloc allowed).
__device__ float   g_deg  [MAXN];
__device__ float   g_dinv [MAXN];
__device__ int     g_fillc[MAXN];
__device__ int     g_rowptr[MAXN + 1];
__device__ int     g_bsum [(MAXN + SCAN_B - 1) / SCAN_B + 1];
__device__ int     g_adj  [MAXE];
__device__ __half2 g_hsh [(size_t)MAXN * (HDIM / 2)];  // row-scaled messages (fp16)
__device__ float4  g_agg4[(size_t)MAXN * (HDIM / 4)];  // aggregation result (fp32)
__device__ int     g_is64;                             // edge-index dtype flag

// ---------------------------------------------------------------------------
// 1) init + dtype probe. int64 data => first 64 words all in [0, MAXN)
// ---------------------------------------------------------------------------
__global__ void init_kernel(const void* __restrict__ ei, int N) {
    int i = blockIdx.x * blockDim.x + threadIdx.x;
    if (i < N) g_deg[i] = 1.0f;
    if (i == 0) {
        const long long* p = (const long long*)ei;
        int is64 = 1;
        #pragma unroll 1
        for (int k = 0; k < 64; k++) {
            long long v = p[k];
            if (v < 0 || v >= MAXN) { is64 = 0; break; }
        }
        g_is64 = is64;
    }
}

// ---------------------------------------------------------------------------
// 2) degree histogram over dst (2 edges/thread, vector index loads)
// ---------------------------------------------------------------------------
__global__ void deg_scatter_kernel(const void* __restrict__ ei, int E) {
    int t = blockIdx.x * blockDim.x + threadIdx.x;
    int e = 2 * t;
    if (e >= E) return;
    bool two = (e + 1 < E);
    int d0, d1 = 0;
    if (g_is64) {
        const long long* p = (const long long*)ei + E;   // dst array
        if (two && ((E & 1) == 0)) {
            longlong2 dv = ((const longlong2*)p)[t];
            d0 = (int)dv.x; d1 = (int)dv.y;
        } else {
            d0 = (int)p[e];
            if (two) d1 = (int)p[e + 1];
        }
    } else {
        const int* p = (const int*)ei + E;
        if (two && ((E & 1) == 0)) {
            int2 dv = ((const int2*)p)[t];
            d0 = dv.x; d1 = dv.y;
        } else {
            d0 = p[e];
            if (two) d1 = p[e + 1];
        }
    }
    atomicAdd(&g_deg[d0], 1.0f);
    if (two) atomicAdd(&g_deg[d1], 1.0f);
}

// ---------------------------------------------------------------------------
// 3) CSR build: exclusive scan of edge counts (deg-1); dinv folded into scan1;
//    fillc = rowptr folded into scan3.
// ---------------------------------------------------------------------------
__global__ void scan1_kernel(int N) {
    __shared__ int s[SCAN_B];
    int i = blockIdx.x * SCAN_B + threadIdx.x;
    float degv = (i < N) ? g_deg[i] : 1.0f;
    if (i < N) g_dinv[i] = rsqrtf(degv);
    int v = (i < N) ? (int)degv - 1 : 0;         // edge count into node i
    s[threadIdx.x] = v;
    __syncthreads();
    #pragma unroll
    for (int off = 1; off < SCAN_B; off <<= 1) {
        int t = (threadIdx.x >= off) ? s[threadIdx.x - off] : 0;
        __syncthreads();
        s[threadIdx.x] += t;
        __syncthreads();
    }
    if (i < N) g_rowptr[i] = s[threadIdx.x] - v;            // exclusive
    if (threadIdx.x == SCAN_B - 1) g_bsum[blockIdx.x] = s[SCAN_B - 1];
}

__global__ void scan2_kernel(int nblocks) {
    __shared__ int s[512];
    int v = (threadIdx.x < nblocks) ? g_bsum[threadIdx.x] : 0;
    s[threadIdx.x] = v;
    __syncthreads();
    #pragma unroll
    for (int off = 1; off < 512; off <<= 1) {
        int t = (threadIdx.x >= off) ? s[threadIdx.x - off] : 0;
        __syncthreads();
        s[threadIdx.x] += t;
        __syncthreads();
    }
    if (threadIdx.x < nblocks) g_bsum[threadIdx.x] = s[threadIdx.x] - v;  // exclusive
}

__global__ void scan3_kernel(int N, int E) {
    int i = blockIdx.x * SCAN_B + threadIdx.x;
    if (i < N) {
        int rp = g_rowptr[i] + g_bsum[blockIdx.x];
        g_rowptr[i] = rp;
        g_fillc[i]  = rp;          // fill kernel bumps this directly
    }
    if (i == 0) g_rowptr[N] = E;
}

__global__ void fill_kernel(const void* __restrict__ ei, int E) {
    int t = blockIdx.x * blockDim.x + threadIdx.x;
    int e = 2 * t;
    if (e >= E) return;
    bool two = (e + 1 < E);
    int s0, s1 = 0, d0, d1 = 0;
    if (g_is64) {
        const long long* p = (const long long*)ei;
        if (two && ((E & 1) == 0)) {
            longlong2 sv = ((const longlong2*)p)[t];
            longlong2 dv = ((const longlong2*)(p + E))[t];
            s0 = (int)sv.x; s1 = (int)sv.y; d0 = (int)dv.x; d1 = (int)dv.y;
        } else {
            s0 = (int)p[e]; d0 = (int)p[E + e];
            if (two) { s1 = (int)p[e + 1]; d1 = (int)p[E + e + 1]; }
        }
    } else {
        const int* p = (const int*)ei;
        if (two && ((E & 1) == 0)) {
            int2 sv = ((const int2*)p)[t];
            int2 dv = ((const int2*)(p + E))[t];
            s0 = sv.x; s1 = sv.y; d0 = dv.x; d1 = dv.y;
        } else {
            s0 = p[e]; d0 = p[E + e];
            if (two) { s1 = p[e + 1]; d1 = p[E + e + 1]; }
        }
    }
    int pos0 = atomicAdd(&g_fillc[d0], 1);
    g_adj[pos0] = s0;
    if (two) {
        int pos1 = atomicAdd(&g_fillc[d1], 1);
        g_adj[pos1] = s1;
    }
}

// ---------------------------------------------------------------------------
// 4) transform1: hs = half((x @ W1) * dinv[row])
// ---------------------------------------------------------------------------
__global__ void transform1_kernel(const float* __restrict__ x,
                                  const float* __restrict__ W1,
                                  int N) {
    __shared__ float Ws[FIN * HDIM];          // 32 KB
    __shared__ float xs[8][4][FIN];           // 16 KB
    const int tid = threadIdx.x;

    for (int i = tid; i < FIN * HDIM / 4; i += 256)
        ((float4*)Ws)[i] = ((const float4*)W1)[i];
    __syncthreads();

    const int w = tid >> 5, l = tid & 31;
    const int rowBase = blockIdx.x * 32 + w * 4;

    #pragma unroll
    for (int r = 0; r < 4; r++) {
        int row = rowBase + r;
        if (row < N)
            ((float4*)xs[w][r])[l] = ((const float4*)(x + (size_t)row * FIN))[l];
    }
    __syncwarp();

    float2 acc[4] = {{0.f,0.f},{0.f,0.f},{0.f,0.f},{0.f,0.f}};
    const float2* Ws2 = (const float2*)Ws;
    #pragma unroll 8
    for (int k = 0; k < FIN; k++) {
        float2 wv = Ws2[k * 32 + l];
        #pragma unroll
        for (int r = 0; r < 4; r++) {
            float xv = xs[w][r][k];
            acc[r].x = fmaf(xv, wv.x, acc[r].x);
            acc[r].y = fmaf(xv, wv.y, acc[r].y);
        }
    }

    #pragma unroll
    for (int r = 0; r < 4; r++) {
        int row = rowBase + r;
        if (row < N) {
            float d = g_dinv[row];
            g_hsh[(size_t)row * 32 + l] =
                __floats2half2_rn(acc[r].x * d, acc[r].y * d);
        }
    }
}

// ---------------------------------------------------------------------------
// 5) aggregation (gather): agg[i] = hs[i] + sum_{src in adj(i)} hs[src]
//    warp per node; lane = (slot 0..3, chunk 0..7); 4 neighbors per step,
//    LDG.128 per lane (16B of one neighbor row); fp32 accum; cross-slot
//    reduction at the end.
// ---------------------------------------------------------------------------
__global__ void agg_kernel(int N) {
    int node = (blockIdx.x * blockDim.x + threadIdx.x) >> 5;
    if (node >= N) return;
    const int l     = threadIdx.x & 31;
    const int slot  = l >> 3;       // which neighbor in the quad
    const int chunk = l & 7;        // which 16B of the 128B row
    const char* hbase = (const char*)g_hsh;
    const unsigned laneoff = chunk * 16;

    float2 a0 = {0.f,0.f}, a1 = {0.f,0.f}, a2 = {0.f,0.f}, a3 = {0.f,0.f};

    // self loop (slot 0 lanes only, so it is counted once)
    if (slot == 0) {
        float4 raw = *(const float4*)(hbase + (size_t)node * 128 + laneoff);
        const __half2* h = (const __half2*)&raw;
        float2 v;
        v = __half22float2(h[0]); a0.x += v.x; a0.y += v.y;
        v = __half22float2(h[1]); a1.x += v.x; a1.y += v.y;
        v = __half22float2(h[2]); a2.x += v.x; a2.y += v.y;
        v = __half22float2(h[3]); a3.x += v.x; a3.y += v.y;
    }

    int j = g_rowptr[node];
    const int end = g_rowptr[node + 1];
    while (j < end) {
        int navail = min(32, end - j);
        int idx = (l < navail) ? g_adj[j + l] : 0;
        int steps = (navail + 3) >> 2;
        #pragma unroll 4
        for (int k = 0; k < steps; k++) {
            int nb = (k << 2) + slot;
            int s = __shfl_sync(0xFFFFFFFFu, idx, nb & 31);
            if (nb < navail) {
                float4 raw = *(const float4*)(hbase + (size_t)s * 128 + laneoff);
                const __half2* h = (const __half2*)&raw;
                float2 v;
                v = __half22float2(h[0]); a0.x += v.x; a0.y += v.y;
                v = __half22float2(h[1]); a1.x += v.x; a1.y += v.y;
                v = __half22float2(h[2]); a2.x += v.x; a2.y += v.y;
                v = __half22float2(h[3]); a3.x += v.x; a3.y += v.y;
            }
        }
        j += navail;
    }

    // reduce across the 4 slots (lanes xor 8 and 16)
    #pragma unroll
    for (int d = 8; d <= 16; d <<= 1) {
        a0.x += __shfl_xor_sync(0xFFFFFFFFu, a0.x, d);
        a0.y += __shfl_xor_sync(0xFFFFFFFFu, a0.y, d);
        a1.x += __shfl_xor_sync(0xFFFFFFFFu, a1.x, d);
        a1.y += __shfl_xor_sync(0xFFFFFFFFu, a1.y, d);
        a2.x += __shfl_xor_sync(0xFFFFFFFFu, a2.x, d);
        a2.y += __shfl_xor_sync(0xFFFFFFFFu, a2.y, d);
        a3.x += __shfl_xor_sync(0xFFFFFFFFu, a3.x, d);
        a3.y += __shfl_xor_sync(0xFFFFFFFFu, a3.y, d);
    }

    if (slot == 0) {   // lanes 0..7 write the 256B row
        float4* out = (float4*)((char*)g_agg4 + (size_t)node * 256 + chunk * 32);
        out[0] = make_float4(a0.x, a0.y, a1.x, a1.y);
        out[1] = make_float4(a2.x, a2.y, a3.x, a3.y);
    }
}

// ---------------------------------------------------------------------------
// 6) transform2: t = relu(dinv*agg1 + b1); hs = half((t @ W2) * dinv)
// ---------------------------------------------------------------------------
__global__ void transform2_kernel(const float* __restrict__ W2,
                                  const float* __restrict__ b1,
                                  int N) {
    __shared__ float Ws[HDIM * HDIM];         // 16 KB
    __shared__ float ts[8][4][HDIM];          // 8 KB
    const int tid = threadIdx.x;

    for (int i = tid; i < HDIM * HDIM / 4; i += 256)
        ((float4*)Ws)[i] = ((const float4*)W2)[i];
    __syncthreads();

    const int w = tid >> 5, l = tid & 31;
    const int rowBase = blockIdx.x * 32 + w * 4;
    const float2 bv = ((const float2*)b1)[l];
    const float* g_agg = (const float*)g_agg4;

    #pragma unroll
    for (int r = 0; r < 4; r++) {
        int row = rowBase + r;
        if (row < N) {
            float d = g_dinv[row];
            float2 av = ((const float2*)(g_agg + (size_t)row * HDIM))[l];
            float2 tv;
            tv.x = fmaxf(fmaf(d, av.x, bv.x), 0.f);
            tv.y = fmaxf(fmaf(d, av.y, bv.y), 0.f);
            ((float2*)ts[w][r])[l] = tv;
        }
    }
    __syncwarp();

    float2 acc[4] = {{0.f,0.f},{0.f,0.f},{0.f,0.f},{0.f,0.f}};
    const float2* Ws2 = (const float2*)Ws;
    #pragma unroll 8
    for (int k = 0; k < HDIM; k++) {
        float2 wv = Ws2[k * 32 + l];
        #pragma unroll
        for (int r = 0; r < 4; r++) {
            float tv = ts[w][r][k];
            acc[r].x = fmaf(tv, wv.x, acc[r].x);
            acc[r].y = fmaf(tv, wv.y, acc[r].y);
        }
    }

    #pragma unroll
    for (int r = 0; r < 4; r++) {
        int row = rowBase + r;
        if (row < N) {
            float d = g_dinv[row];
            g_hsh[(size_t)row * 32 + l] =
                __floats2half2_rn(acc[r].x * d, acc[r].y * d);
        }
    }
}

// ---------------------------------------------------------------------------
// 7) final: out[i] = relu(dinv*agg2 + b2) @ Wlin + blin   (warp per row)
// ---------------------------------------------------------------------------
__global__ void final_kernel(const float* __restrict__ b2,
                             const float* __restrict__ Wlin,
                             const float* __restrict__ blin,
                             float* __restrict__ out, int N) {
    int warpG = (blockIdx.x * blockDim.x + threadIdx.x) >> 5;
    int l = threadIdx.x & 31;
    if (warpG >= N) return;
    int row = warpG;
    const float* g_agg = (const float*)g_agg4;
    float d = g_dinv[row];
    float2 av = ((const float2*)(g_agg + (size_t)row * HDIM))[l];
    float2 bv = ((const float2*)b2)[l];
    float2 wv = ((const float2*)Wlin)[l];
    float h0 = fmaxf(fmaf(d, av.x, bv.x), 0.f);
    float h1 = fmaxf(fmaf(d, av.y, bv.y), 0.f);
    float s = h0 * wv.x + h1 * wv.y;
    #pragma unroll
    for (int off = 16; off > 0; off >>= 1)
        s += __shfl_xor_sync(0xFFFFFFFFu, s, off);
    if (l == 0) out[row] = s + blin[0];
}

// ---------------------------------------------------------------------------
extern "C" void kernel_launch(void* const* d_in, const int* in_sizes, int n_in,
                              void* d_out, int out_size) {
    const float* x    = (const float*)d_in[0];
    const void*  ei   = d_in[1];
    const float* W1   = (const float*)d_in[2];
    const float* b1   = (const float*)d_in[3];
    const float* W2   = (const float*)d_in[4];
    const float* b2   = (const float*)d_in[5];
    const float* Wlin = (const float*)d_in[6];
    const float* blin = (const float*)d_in[7];
    float*       out  = (float*)d_out;

    const int N = in_sizes[0] / FIN;
    const int E = in_sizes[1] / 2;

    const int nb  = (N + SCAN_B - 1) / SCAN_B;       // scan blocks
    const int eb2 = ((E + 1) / 2 + 255) / 256;       // 2 edges per thread
    const int tb  = (N + 31) / 32;                   // 32 rows per block
    const int ab  = (N * 32 + 255) / 256;            // warp per node
    const int fb  = (N + 7) / 8;

    init_kernel       <<<nb, SCAN_B>>>(ei, N);
    deg_scatter_kernel<<<eb2, 256>>>(ei, E);

    scan1_kernel      <<<nb, SCAN_B>>>(N);
    scan2_kernel      <<<1, 512>>>(nb);
    scan3_kernel      <<<nb, SCAN_B>>>(N, E);
    fill_kernel       <<<eb2, 256>>>(ei, E);

    transform1_kernel <<<tb, 256>>>(x, W1, N);
    agg_kernel        <<<ab, 256>>>(N);

    transform2_kernel <<<tb, 256>>>(W2, b1, N);
    agg_kernel        <<<ab, 256>>>(N);

    final_kernel      <<<fb, 256>>>(b2, Wlin, blin, out, N);
}